// round 2
// baseline (speedup 1.0000x reference)
#include <cuda_runtime.h>
#include <cstdint>
#include <cstdio>

#define BATCH   2
#define SEQ     512
#define DMODEL  512
#define DSTATE  64
#define DCONV   4
#define DINNER  1024
#define NHEADS  16
#define HEADDIM 64
#define DIP     2192      // D_IN_PROJ = 2*1024 + 2*64 + 16
#define CONVDIM 1152      // D_INNER + 2*D_STATE
#define VOCAB   32768
#define VB      4         // virtual batch: [fwd b0, fwd b1, bwd b0, bwd b1]
#define M1      (VB*SEQ)  // 2048
#define MT      (BATCH*SEQ) // 1024

// ---------------- scratch (device globals; no allocation allowed) -------------
__device__ float g_X[MT*DMODEL];
__device__ float g_Xcat[M1*DMODEL];
__device__ float g_Z[M1*DIP];
__device__ float g_xBC[M1*CONVDIM];
__device__ float g_dt[M1*NHEADS];
__device__ float g_dA[M1*NHEADS];
__device__ float g_y[M1*DINNER];
__device__ float g_yn[M1*DINNER];
__device__ float g_Ycat[M1*DMODEL];
__device__ float g_Xf[MT*DMODEL];
__device__ float g_Xb[MT*DMODEL];
__device__ float g_XC[MT*2*DMODEL];
__device__ float g_G[MT*DMODEL];
__device__ float g_H[MT*DMODEL];
__device__ int   g_len[BATCH];

// ---------------- helpers ----------------------------------------------------
__device__ __forceinline__ float siluf(float x){ return x / (1.f + expf(-x)); }
__device__ __forceinline__ float sigmoidf_(float x){ return 1.f / (1.f + expf(-x)); }

__device__ __forceinline__ float block_reduce_sum(float v){
    __shared__ float sh[8];
    __shared__ float tot;
    #pragma unroll
    for (int o = 16; o > 0; o >>= 1) v += __shfl_xor_sync(0xffffffffu, v, o);
    int w = threadIdx.x >> 5;
    if ((threadIdx.x & 31) == 0) sh[w] = v;
    __syncthreads();
    if (threadIdx.x < 32) {
        float t = (threadIdx.x < 8) ? sh[threadIdx.x] : 0.f;
        #pragma unroll
        for (int o = 4; o > 0; o >>= 1) t += __shfl_xor_sync(0xffffffffu, t, o);
        if (threadIdx.x == 0) tot = t;
    }
    __syncthreads();
    return tot;
}

// ---------------- small kernels ----------------------------------------------
__global__ void k_lengths(const unsigned char* __restrict__ mask){
    // blockIdx.x = b. mask entries are 0 for valid tokens (all-zero in this dataset,
    // so any byte-level interpretation of the bool array yields the correct count).
    __shared__ float dummy;
    (void)dummy;
    int b = blockIdx.x;
    int cnt = 0;
    for (int l = threadIdx.x; l < SEQ; l += blockDim.x)
        cnt += (mask[b*SEQ + l] == 0) ? 1 : 0;
    float total = block_reduce_sum((float)cnt);
    if (threadIdx.x == 0) g_len[b] = (int)(total + 0.5f);
}

__global__ void k_embed(const int* __restrict__ ids, const float* __restrict__ emb){
    int i = blockIdx.x*blockDim.x + threadIdx.x;
    if (i >= MT*DMODEL) return;
    int t = i / DMODEL, d = i % DMODEL;
    g_X[i] = emb[(size_t)ids[t]*DMODEL + d];
}

__global__ void k_build_xcat(){
    int i = blockIdx.x*blockDim.x + threadIdx.x;
    if (i >= M1*DMODEL) return;
    int d = i % DMODEL; int m = i / DMODEL;
    int l = m % SEQ; int vb = m / SEQ;
    float v;
    if (vb < BATCH) {
        v = g_X[((size_t)vb*SEQ + l)*DMODEL + d];
    } else {
        int b = vb - BATCH;
        int len = g_len[b];
        int rl = (l < len) ? (len - 1 - l) : l;
        v = g_X[((size_t)b*SEQ + rl)*DMODEL + d];
    }
    g_Xcat[i] = v;
}

// depthwise causal conv width 4 + silu, reading the xBC slice of g_Z
__global__ void k_conv(const float* __restrict__ cw, const float* __restrict__ cb){
    int i = blockIdx.x*blockDim.x + threadIdx.x;
    if (i >= M1*CONVDIM) return;
    int c = i % CONVDIM; int m = i / CONVDIM; int l = m % SEQ;
    int mbase = m - l;
    float acc = cb[c];
    #pragma unroll
    for (int k = 0; k < DCONV; k++){
        int ls = l - (DCONV-1) + k;
        if (ls >= 0)
            acc += g_Z[(size_t)(mbase + ls)*DIP + DINNER + c] * cw[c*DCONV + k];
    }
    g_xBC[i] = siluf(acc);
}

__global__ void k_dt(const float* __restrict__ dtb, const float* __restrict__ alog){
    int i = blockIdx.x*blockDim.x + threadIdx.x;
    if (i >= M1*NHEADS) return;
    int h = i % NHEADS; int m = i / NHEADS;
    float raw = g_Z[(size_t)m*DIP + DINNER + CONVDIM + h] + dtb[h];
    float dt = (raw > 20.f) ? raw : log1pf(expf(raw));
    float A = -expf(alog[h]);
    g_dt[i] = dt;
    g_dA[i] = expf(dt * A);
}

// SSD scan: one block per (vb, head). State (64x64) in registers (16/thread).
__global__ void __launch_bounds__(256) k_scan(const float* __restrict__ dss){
    int vb = blockIdx.x / NHEADS;
    int h  = blockIdx.x % NHEADS;
    int tid = threadIdx.x;
    int p = tid >> 2;          // 0..63 head-dim row
    int g = tid & 3;           // 0..3 state-dim quarter
    int n0 = g * 16;

    float hst[16];
    #pragma unroll
    for (int j = 0; j < 16; j++) hst[j] = 0.f;

    __shared__ float sB[2][DSTATE];
    __shared__ float sC[2][DSTATE];

    float Dh = dss[h];
    const float* xbase = g_xBC + (size_t)vb*SEQ*CONVDIM;

    // preload t=0
    if (tid < 64)            sB[0][tid]     = xbase[DINNER + tid];
    else if (tid < 128)      sC[0][tid-64]  = xbase[DINNER + DSTATE + (tid-64)];

    for (int t = 0; t < SEQ; t++){
        __syncthreads();
        int cur = t & 1, nxt = cur ^ 1;
        if (t + 1 < SEQ){
            const float* xb = xbase + (size_t)(t+1)*CONVDIM;
            if (tid < 64)        sB[nxt][tid]    = xb[DINNER + tid];
            else if (tid < 128)  sC[nxt][tid-64] = xb[DINNER + DSTATE + (tid-64)];
        }
        int m = vb*SEQ + t;
        float dt = g_dt[(size_t)m*NHEADS + h];
        float dA = g_dA[(size_t)m*NHEADS + h];
        float xp = xbase[(size_t)t*CONVDIM + h*HEADDIM + p];
        float dtx = dt * xp;
        float acc = 0.f;
        #pragma unroll
        for (int j = 0; j < 16; j++){
            hst[j] = hst[j]*dA + dtx * sB[cur][n0 + j];
            acc   += hst[j] * sC[cur][n0 + j];
        }
        acc += __shfl_xor_sync(0xffffffffu, acc, 1);
        acc += __shfl_xor_sync(0xffffffffu, acc, 2);
        if (g == 0)
            g_y[(size_t)m*DINNER + h*HEADDIM + p] = acc + Dh * xp;
    }
}

// y = rmsnorm(y * silu(z)) * norm_w ; one block per token row (D=1024)
__global__ void __launch_bounds__(256) k_gnorm(const float* __restrict__ nw){
    int m = blockIdx.x;
    float v[4];
    float ss = 0.f;
    #pragma unroll
    for (int j = 0; j < 4; j++){
        int c = threadIdx.x + j*256;
        float z = g_Z[(size_t)m*DIP + c];
        float val = g_y[(size_t)m*DINNER + c] * siluf(z);
        v[j] = val;
        ss += val * val;
    }
    float total = block_reduce_sum(ss);
    float scale = rsqrtf(total / (float)DINNER + 1e-5f);
    #pragma unroll
    for (int j = 0; j < 4; j++){
        int c = threadIdx.x + j*256;
        g_yn[(size_t)m*DINNER + c] = v[j] * scale * nw[c];
    }
}

// split Ycat into X_f / un-flipped X_b, and build concat buffer for the gate GEMM
__global__ void k_unflip(){
    int i = blockIdx.x*blockDim.x + threadIdx.x;
    if (i >= MT*DMODEL) return;
    int d = i % DMODEL; int m = i / DMODEL;
    int l = m % SEQ; int b = m / SEQ;
    float xf = g_Ycat[((size_t)b*SEQ + l)*DMODEL + d];
    int len = g_len[b];
    int rl = (l < len) ? (len - 1 - l) : l;
    float xb = g_Ycat[((size_t)(BATCH + b)*SEQ + rl)*DMODEL + d];
    g_Xf[i] = xf;
    g_Xb[i] = xb;
    g_XC[(size_t)m*(2*DMODEL) + d]          = xf;
    g_XC[(size_t)m*(2*DMODEL) + DMODEL + d] = xb;
}

__global__ void k_combine(){
    int i = blockIdx.x*blockDim.x + threadIdx.x;
    if (i >= MT*DMODEL) return;
    float gg = sigmoidf_(g_G[i]);
    g_X[i] = gg * g_Xf[i] + (1.f - gg) * g_Xb[i];
}

// final rmsnorm, D=512, g_X -> g_H
__global__ void __launch_bounds__(256) k_rmsnorm_final(const float* __restrict__ w){
    int m = blockIdx.x;
    float v[2];
    float ss = 0.f;
    #pragma unroll
    for (int j = 0; j < 2; j++){
        int c = threadIdx.x + j*256;
        float x = g_X[(size_t)m*DMODEL + c];
        v[j] = x;
        ss += x * x;
    }
    float total = block_reduce_sum(ss);
    float scale = rsqrtf(total / (float)DMODEL + 1e-5f);
    #pragma unroll
    for (int j = 0; j < 2; j++){
        int c = threadIdx.x + j*256;
        g_H[(size_t)m*DMODEL + c] = v[j] * scale * w[c];
    }
}

// ---------------- GEMM: C[m,n] = sum_k A[m,k]*B[n,k] (+bias[n]) (+resid[m,n]) --
#define BM 64
#define BN 64
#define BK 16
__global__ void __launch_bounds__(256) k_gemm(
    const float* __restrict__ A, const float* __restrict__ B,
    const float* __restrict__ bias, const float* __restrict__ resid,
    float* __restrict__ C, int M, int N, int K)
{
    __shared__ float As[BK][BM+4];
    __shared__ float Bs[BK][BN+4];
    int tid = threadIdx.x;
    int tx = tid & 15, ty = tid >> 4;
    int m0 = blockIdx.y * BM, n0 = blockIdx.x * BN;

    int lr = tid >> 2;          // 0..63
    int lk = (tid & 3) * 4;     // 0,4,8,12

    const float* Aptr = A + (size_t)(m0 + lr)*K + lk;
    bool bvalid = (n0 + lr) < N;
    const float* Bptr = B + (size_t)(n0 + lr)*K + lk;

    float acc[4][4];
    #pragma unroll
    for (int i = 0; i < 4; i++)
        #pragma unroll
        for (int j = 0; j < 4; j++) acc[i][j] = 0.f;

    for (int k0 = 0; k0 < K; k0 += BK){
        float4 av = *(const float4*)(Aptr + k0);
        float4 bv = bvalid ? *(const float4*)(Bptr + k0) : make_float4(0.f,0.f,0.f,0.f);
        __syncthreads();
        As[lk+0][lr] = av.x; As[lk+1][lr] = av.y; As[lk+2][lr] = av.z; As[lk+3][lr] = av.w;
        Bs[lk+0][lr] = bv.x; Bs[lk+1][lr] = bv.y; Bs[lk+2][lr] = bv.z; Bs[lk+3][lr] = bv.w;
        __syncthreads();
        #pragma unroll
        for (int k = 0; k < BK; k++){
            float4 a = *(const float4*)&As[k][ty*4];
            float4 b = *(const float4*)&Bs[k][tx*4];
            float af[4] = {a.x, a.y, a.z, a.w};
            float bf[4] = {b.x, b.y, b.z, b.w};
            #pragma unroll
            for (int i = 0; i < 4; i++)
                #pragma unroll
                for (int j = 0; j < 4; j++)
                    acc[i][j] += af[i] * bf[j];
        }
    }

    #pragma unroll
    for (int i = 0; i < 4; i++){
        int m = m0 + ty*4 + i;
        #pragma unroll
        for (int j = 0; j < 4; j++){
            int n = n0 + tx*4 + j;
            if (n < N){
                float v = acc[i][j];
                if (bias)  v += bias[n];
                if (resid) v += resid[(size_t)m*N + n];
                C[(size_t)m*N + n] = v;
            }
        }
    }
}

// ---------------- driver ------------------------------------------------------
static float* sym(const void* s){ void* p = nullptr; cudaGetSymbolAddress(&p, s); return (float*)p; }

extern "C" void kernel_launch(void* const* d_in, const int* in_sizes, int n_in,
                              void* d_out, int out_size)
{
    const int*            ids   = (const int*)d_in[0];
    const unsigned char*  mask  = (const unsigned char*)d_in[1];
    const float*          emb   = (const float*)d_in[2];
    const float*          wi    = (const float*)d_in[3];   // [L, DIP, DMODEL]
    const float*          cw    = (const float*)d_in[4];   // [L, CONVDIM, 4]
    const float*          cb    = (const float*)d_in[5];
    const float*          dtb   = (const float*)d_in[6];
    const float*          alog  = (const float*)d_in[7];
    const float*          dss   = (const float*)d_in[8];
    const float*          nw    = (const float*)d_in[9];
    const float*          wo    = (const float*)d_in[10];  // [L, DMODEL, DINNER]
    const float*          aggw  = (const float*)d_in[11];  // [DMODEL, 2*DMODEL]
    const float*          aggb  = (const float*)d_in[12];
    const float*          nfw   = (const float*)d_in[13];
    const float*          lmw   = (const float*)d_in[14];  // [VOCAB, DMODEL]
    const float*          lmb   = (const float*)d_in[15];
    float*                out   = (float*)d_out;

    float* pXcat = sym(g_Xcat);
    float* pZ    = sym(g_Z);
    float* pyn   = sym(g_yn);
    float* pYcat = sym(g_Ycat);
    float* pXC   = sym(g_XC);
    float* pG    = sym(g_G);
    float* pH    = sym(g_H);

    k_lengths<<<BATCH, 256>>>(mask);
    k_embed<<<(MT*DMODEL + 255)/256, 256>>>(ids, emb);

    for (int l = 0; l < 2; l++){
        k_build_xcat<<<(M1*DMODEL + 255)/256, 256>>>();

        // zxbcdt = Xcat @ Wi^T
        k_gemm<<<dim3((DIP + BN - 1)/BN, M1/BM), 256>>>(
            pXcat, wi + (size_t)l*DIP*DMODEL, nullptr, nullptr, pZ, M1, DIP, DMODEL);

        k_conv<<<(M1*CONVDIM + 255)/256, 256>>>(cw + (size_t)l*CONVDIM*DCONV,
                                                cb + (size_t)l*CONVDIM);
        k_dt<<<(M1*NHEADS + 255)/256, 256>>>(dtb + l*NHEADS, alog + l*NHEADS);

        k_scan<<<VB*NHEADS, 256>>>(dss + l*NHEADS);

        k_gnorm<<<M1, 256>>>(nw + (size_t)l*DINNER);

        // Ycat = yn @ Wo^T + Xcat (residual)
        k_gemm<<<dim3(DMODEL/BN, M1/BM), 256>>>(
            pyn, wo + (size_t)l*DMODEL*DINNER, nullptr, pXcat, pYcat, M1, DMODEL, DINNER);

        k_unflip<<<(MT*DMODEL + 255)/256, 256>>>();

        // gate logits = [Xf|Xb] @ aggr_w^T + aggr_b
        k_gemm<<<dim3(DMODEL/BN, MT/BM), 256>>>(
            pXC, aggw, aggb, nullptr, pG, MT, DMODEL, 2*DMODEL);

        k_combine<<<(MT*DMODEL + 255)/256, 256>>>();
    }

    k_rmsnorm_final<<<MT, 256>>>(nfw);

    // logits = H @ lm_head_w^T + lm_head_b
    k_gemm<<<dim3(VOCAB/BN, MT/BM), 256>>>(
        pH, lmw, lmb, nullptr, out, MT, VOCAB, DMODEL);

    (void)n_in; (void)in_sizes; (void)out_size;
}

// round 3
// speedup vs baseline: 1.1925x; 1.1925x over previous
#include <cuda_runtime.h>
#include <cstdint>
#include <cstdio>

#define BATCH   2
#define SEQ     512
#define DMODEL  512
#define DSTATE  64
#define DCONV   4
#define DINNER  1024
#define NHEADS  16
#define HEADDIM 64
#define DIP     2192      // D_IN_PROJ = 2*1024 + 2*64 + 16
#define CONVDIM 1152      // D_INNER + 2*D_STATE
#define VOCAB   32768
#define VB      4         // virtual batch: [fwd b0, fwd b1, bwd b0, bwd b1]
#define M1      (VB*SEQ)  // 2048
#define MT      (BATCH*SEQ) // 1024
#define SPLITK  4

// ---------------- scratch (device globals; no allocation allowed) -------------
__device__ float g_X[MT*DMODEL];
__device__ float g_Xcat[M1*DMODEL];
__device__ float g_Z[M1*DIP];
__device__ float g_xBC[M1*CONVDIM];
__device__ float g_dt[M1*NHEADS];
__device__ float g_dA[M1*NHEADS];
__device__ float g_y[M1*DINNER];
__device__ float g_yn[M1*DINNER];
__device__ float g_Ycat[M1*DMODEL];
__device__ float g_Xf[MT*DMODEL];
__device__ float g_Xb[MT*DMODEL];
__device__ float g_XC[MT*2*DMODEL];
__device__ float g_G[MT*DMODEL];
__device__ float g_H[MT*DMODEL];
__device__ float g_SK[SPLITK*M1*DMODEL];   // split-K partials (max M1 x DMODEL)
__device__ int   g_len[BATCH];

// ---------------- helpers ----------------------------------------------------
__device__ __forceinline__ float siluf(float x){ return x / (1.f + expf(-x)); }
__device__ __forceinline__ float sigmoidf_(float x){ return 1.f / (1.f + expf(-x)); }

__device__ __forceinline__ float block_reduce_sum(float v){
    __shared__ float sh[8];
    __shared__ float tot;
    #pragma unroll
    for (int o = 16; o > 0; o >>= 1) v += __shfl_xor_sync(0xffffffffu, v, o);
    int w = threadIdx.x >> 5;
    if ((threadIdx.x & 31) == 0) sh[w] = v;
    __syncthreads();
    if (threadIdx.x < 32) {
        float t = (threadIdx.x < 8) ? sh[threadIdx.x] : 0.f;
        #pragma unroll
        for (int o = 4; o > 0; o >>= 1) t += __shfl_xor_sync(0xffffffffu, t, o);
        if (threadIdx.x == 0) tot = t;
    }
    __syncthreads();
    return tot;
}

// ---------------- small kernels ----------------------------------------------
__global__ void k_lengths(const unsigned char* __restrict__ mask){
    int b = blockIdx.x;
    int cnt = 0;
    for (int l = threadIdx.x; l < SEQ; l += blockDim.x)
        cnt += (mask[b*SEQ + l] == 0) ? 1 : 0;
    float total = block_reduce_sum((float)cnt);
    if (threadIdx.x == 0) g_len[b] = (int)(total + 0.5f);
}

__global__ void k_embed(const int* __restrict__ ids, const float* __restrict__ emb){
    int i = blockIdx.x*blockDim.x + threadIdx.x;
    if (i >= MT*DMODEL) return;
    int t = i / DMODEL, d = i % DMODEL;
    g_X[i] = emb[(size_t)ids[t]*DMODEL + d];
}

__global__ void k_build_xcat(){
    int i = blockIdx.x*blockDim.x + threadIdx.x;
    if (i >= M1*DMODEL) return;
    int d = i % DMODEL; int m = i / DMODEL;
    int l = m % SEQ; int vb = m / SEQ;
    float v;
    if (vb < BATCH) {
        v = g_X[((size_t)vb*SEQ + l)*DMODEL + d];
    } else {
        int b = vb - BATCH;
        int len = g_len[b];
        int rl = (l < len) ? (len - 1 - l) : l;
        v = g_X[((size_t)b*SEQ + rl)*DMODEL + d];
    }
    g_Xcat[i] = v;
}

// depthwise causal conv width 4 + silu, reading the xBC slice of g_Z
__global__ void k_conv(const float* __restrict__ cw, const float* __restrict__ cb){
    int i = blockIdx.x*blockDim.x + threadIdx.x;
    if (i >= M1*CONVDIM) return;
    int c = i % CONVDIM; int m = i / CONVDIM; int l = m % SEQ;
    int mbase = m - l;
    float acc = cb[c];
    #pragma unroll
    for (int k = 0; k < DCONV; k++){
        int ls = l - (DCONV-1) + k;
        if (ls >= 0)
            acc += g_Z[(size_t)(mbase + ls)*DIP + DINNER + c] * cw[c*DCONV + k];
    }
    g_xBC[i] = siluf(acc);
}

__global__ void k_dt(const float* __restrict__ dtb, const float* __restrict__ alog){
    int i = blockIdx.x*blockDim.x + threadIdx.x;
    if (i >= M1*NHEADS) return;
    int h = i % NHEADS; int m = i / NHEADS;
    float raw = g_Z[(size_t)m*DIP + DINNER + CONVDIM + h] + dtb[h];
    float dt = (raw > 20.f) ? raw : log1pf(expf(raw));
    float A = -expf(alog[h]);
    g_dt[i] = dt;
    g_dA[i] = expf(dt * A);
}

// SSD scan: one block per (vb, head). State (64x64) in registers (16/thread).
__global__ void __launch_bounds__(256) k_scan(const float* __restrict__ dss){
    int vb = blockIdx.x / NHEADS;
    int h  = blockIdx.x % NHEADS;
    int tid = threadIdx.x;
    int p = tid >> 2;          // 0..63 head-dim row
    int g = tid & 3;           // 0..3 state-dim quarter
    int n0 = g * 16;

    float hst[16];
    #pragma unroll
    for (int j = 0; j < 16; j++) hst[j] = 0.f;

    __shared__ float sB[2][DSTATE];
    __shared__ float sC[2][DSTATE];

    float Dh = dss[h];
    const float* xbase = g_xBC + (size_t)vb*SEQ*CONVDIM;

    if (tid < 64)            sB[0][tid]     = xbase[DINNER + tid];
    else if (tid < 128)      sC[0][tid-64]  = xbase[DINNER + DSTATE + (tid-64)];

    for (int t = 0; t < SEQ; t++){
        __syncthreads();
        int cur = t & 1, nxt = cur ^ 1;
        if (t + 1 < SEQ){
            const float* xb = xbase + (size_t)(t+1)*CONVDIM;
            if (tid < 64)        sB[nxt][tid]    = xb[DINNER + tid];
            else if (tid < 128)  sC[nxt][tid-64] = xb[DINNER + DSTATE + (tid-64)];
        }
        int m = vb*SEQ + t;
        float dt = g_dt[(size_t)m*NHEADS + h];
        float dA = g_dA[(size_t)m*NHEADS + h];
        float xp = xbase[(size_t)t*CONVDIM + h*HEADDIM + p];
        float dtx = dt * xp;
        float acc = 0.f;
        #pragma unroll
        for (int j = 0; j < 16; j++){
            hst[j] = hst[j]*dA + dtx * sB[cur][n0 + j];
            acc   += hst[j] * sC[cur][n0 + j];
        }
        acc += __shfl_xor_sync(0xffffffffu, acc, 1);
        acc += __shfl_xor_sync(0xffffffffu, acc, 2);
        if (g == 0)
            g_y[(size_t)m*DINNER + h*HEADDIM + p] = acc + Dh * xp;
    }
}

// y = rmsnorm(y * silu(z)) * norm_w ; one block per token row (D=1024)
__global__ void __launch_bounds__(256) k_gnorm(const float* __restrict__ nw){
    int m = blockIdx.x;
    float v[4];
    float ss = 0.f;
    #pragma unroll
    for (int j = 0; j < 4; j++){
        int c = threadIdx.x + j*256;
        float z = g_Z[(size_t)m*DIP + c];
        float val = g_y[(size_t)m*DINNER + c] * siluf(z);
        v[j] = val;
        ss += val * val;
    }
    float total = block_reduce_sum(ss);
    float scale = rsqrtf(total / (float)DINNER + 1e-5f);
    #pragma unroll
    for (int j = 0; j < 4; j++){
        int c = threadIdx.x + j*256;
        g_yn[(size_t)m*DINNER + c] = v[j] * scale * nw[c];
    }
}

// split Ycat into X_f / un-flipped X_b, and build concat buffer for the gate GEMM
__global__ void k_unflip(){
    int i = blockIdx.x*blockDim.x + threadIdx.x;
    if (i >= MT*DMODEL) return;
    int d = i % DMODEL; int m = i / DMODEL;
    int l = m % SEQ; int b = m / SEQ;
    float xf = g_Ycat[((size_t)b*SEQ + l)*DMODEL + d];
    int len = g_len[b];
    int rl = (l < len) ? (len - 1 - l) : l;
    float xb = g_Ycat[((size_t)(BATCH + b)*SEQ + rl)*DMODEL + d];
    g_Xf[i] = xf;
    g_Xb[i] = xb;
    g_XC[(size_t)m*(2*DMODEL) + d]          = xf;
    g_XC[(size_t)m*(2*DMODEL) + DMODEL + d] = xb;
}

__global__ void k_combine(){
    int i = blockIdx.x*blockDim.x + threadIdx.x;
    if (i >= MT*DMODEL) return;
    float gg = sigmoidf_(g_G[i]);
    g_X[i] = gg * g_Xf[i] + (1.f - gg) * g_Xb[i];
}

// final rmsnorm, D=512, g_X -> g_H
__global__ void __launch_bounds__(256) k_rmsnorm_final(const float* __restrict__ w){
    int m = blockIdx.x;
    float v[2];
    float ss = 0.f;
    #pragma unroll
    for (int j = 0; j < 2; j++){
        int c = threadIdx.x + j*256;
        float x = g_X[(size_t)m*DMODEL + c];
        v[j] = x;
        ss += x * x;
    }
    float total = block_reduce_sum(ss);
    float scale = rsqrtf(total / (float)DMODEL + 1e-5f);
    #pragma unroll
    for (int j = 0; j < 2; j++){
        int c = threadIdx.x + j*256;
        g_H[(size_t)m*DMODEL + c] = v[j] * scale * w[c];
    }
}

// ---------------- GEMM: C[m,n] = sum_k A[m,k]*B[n,k] (+bias[n]) (+resid[m,n]) --
// 128x128 block tile, 8x8 per thread, BK=8, double-buffered, conflict-free LDS.
#define BM 128
#define BN 128
#define BK 8

struct GemmCore {
    float acc[8][8];
};

// Shared GEMM body: computes 128x128 tile accumulators for block (bx, by)
// over k range [kbase, kbase+klen). Writes nothing; fills acc.
__device__ __forceinline__ void gemm_tile(
    const float* __restrict__ A, const float* __restrict__ B,
    int N, int K, int m0, int n0, int kbase, int klen,
    float (&As)[2][BK][BM], float (&Bs)[2][BK][BN],
    float (&acc)[8][8], int tid)
{
    int lr = tid >> 1;           // 0..127: row within tile (for global loads)
    int lk = (tid & 1) * 4;      // 0 or 4: k offset

    const float* Ag = A + (size_t)(m0 + lr)*K + kbase + lk;
    bool bval = (n0 + lr) < N;
    const float* Bg = B + (size_t)(n0 + lr)*K + kbase + lk;

    int lane = tid & 31, warp = tid >> 5;
    int wm = (warp >> 1) * 32;
    int wn = (warp & 1) * 64;
    int tm1 = wm + ((lane >> 3) << 2);   // rows tm1..tm1+3, tm1+16..tm1+19
    int tn1 = wn + ((lane & 7) << 2);    // cols tn1..tn1+3, tn1+32..tn1+35

    float4 pa = *(const float4*)Ag;
    float4 pb = bval ? *(const float4*)Bg : make_float4(0.f,0.f,0.f,0.f);
    #pragma unroll
    for (int j = 0; j < 4; j++){
        As[0][lk+j][lr] = ((float*)&pa)[j];
        Bs[0][lk+j][lr] = ((float*)&pb)[j];
    }
    __syncthreads();

    int nk = klen / BK;
    for (int kt = 0; kt < nk; kt++){
        int cur = kt & 1, nxt = cur ^ 1;
        if (kt + 1 < nk){
            pa = *(const float4*)(Ag + (kt+1)*BK);
            pb = bval ? *(const float4*)(Bg + (kt+1)*BK) : make_float4(0.f,0.f,0.f,0.f);
        }
        #pragma unroll
        for (int k = 0; k < BK; k++){
            float a[8], b[8];
            *(float4*)&a[0] = *(const float4*)&As[cur][k][tm1];
            *(float4*)&a[4] = *(const float4*)&As[cur][k][tm1+16];
            *(float4*)&b[0] = *(const float4*)&Bs[cur][k][tn1];
            *(float4*)&b[4] = *(const float4*)&Bs[cur][k][tn1+32];
            #pragma unroll
            for (int i = 0; i < 8; i++)
                #pragma unroll
                for (int j = 0; j < 8; j++)
                    acc[i][j] = fmaf(a[i], b[j], acc[i][j]);
        }
        if (kt + 1 < nk){
            #pragma unroll
            for (int j = 0; j < 4; j++){
                As[nxt][lk+j][lr] = ((float*)&pa)[j];
                Bs[nxt][lk+j][lr] = ((float*)&pb)[j];
            }
        }
        __syncthreads();
    }
}

__device__ __forceinline__ int row_of(int tm1, int i){ return (i < 4) ? tm1 + i : tm1 + 16 + (i - 4); }
__device__ __forceinline__ int col_of(int tn1, int j){ return (j < 4) ? tn1 + j : tn1 + 32 + (j - 4); }

__global__ void __launch_bounds__(256, 2) k_gemm(
    const float* __restrict__ A, const float* __restrict__ B,
    const float* __restrict__ bias, const float* __restrict__ resid,
    float* __restrict__ C, int M, int N, int K)
{
    __shared__ float As[2][BK][BM];
    __shared__ float Bs[2][BK][BN];
    int tid = threadIdx.x;
    int m0 = blockIdx.y * BM, n0 = blockIdx.x * BN;

    float acc[8][8] = {};
    gemm_tile(A, B, N, K, m0, n0, 0, K, As, Bs, acc, tid);

    int lane = tid & 31, warp = tid >> 5;
    int tm1 = ((warp >> 1) << 5) + ((lane >> 3) << 2);
    int tn1 = ((warp & 1) << 6) + ((lane & 7) << 2);

    if (n0 + BN <= N){
        #pragma unroll
        for (int i = 0; i < 8; i++){
            int m = m0 + row_of(tm1, i);
            #pragma unroll
            for (int jg = 0; jg < 2; jg++){
                int n = n0 + tn1 + jg*32;
                float4 v = *(float4*)&acc[i][jg*4];
                if (bias){
                    float4 bb = *(const float4*)&bias[n];
                    v.x += bb.x; v.y += bb.y; v.z += bb.z; v.w += bb.w;
                }
                if (resid){
                    float4 rr = *(const float4*)&resid[(size_t)m*N + n];
                    v.x += rr.x; v.y += rr.y; v.z += rr.z; v.w += rr.w;
                }
                *(float4*)&C[(size_t)m*N + n] = v;
            }
        }
    } else {
        #pragma unroll
        for (int i = 0; i < 8; i++){
            int m = m0 + row_of(tm1, i);
            #pragma unroll
            for (int j = 0; j < 8; j++){
                int n = n0 + col_of(tn1, j);
                if (n < N){
                    float v = acc[i][j];
                    if (bias)  v += bias[n];
                    if (resid) v += resid[(size_t)m*N + n];
                    C[(size_t)m*N + n] = v;
                }
            }
        }
    }
}

// split-K variant: gridDim.z slices, partials to g_SK[z*M*N + ...]
__global__ void __launch_bounds__(256, 2) k_gemm_sk(
    const float* __restrict__ A, const float* __restrict__ B,
    int M, int N, int K)
{
    __shared__ float As[2][BK][BM];
    __shared__ float Bs[2][BK][BN];
    int tid = threadIdx.x;
    int m0 = blockIdx.y * BM, n0 = blockIdx.x * BN;
    int kchunk = K / SPLITK;
    int kbase = blockIdx.z * kchunk;

    float acc[8][8] = {};
    gemm_tile(A, B, N, K, m0, n0, kbase, kchunk, As, Bs, acc, tid);

    int lane = tid & 31, warp = tid >> 5;
    int tm1 = ((warp >> 1) << 5) + ((lane >> 3) << 2);
    int tn1 = ((warp & 1) << 6) + ((lane & 7) << 2);

    float* Cp = g_SK + (size_t)blockIdx.z * M * N;
    #pragma unroll
    for (int i = 0; i < 8; i++){
        int m = m0 + row_of(tm1, i);
        #pragma unroll
        for (int jg = 0; jg < 2; jg++){
            int n = n0 + tn1 + jg*32;
            if (n + 3 < N)
                *(float4*)&Cp[(size_t)m*N + n] = *(float4*)&acc[i][jg*4];
        }
    }
}

__global__ void k_sk_reduce(const float* __restrict__ bias,
                            const float* __restrict__ resid,
                            float* __restrict__ C, int M, int N)
{
    int i = blockIdx.x*blockDim.x + threadIdx.x;
    if (i >= M*N) return;
    int n = i % N;
    float v = 0.f;
    #pragma unroll
    for (int s = 0; s < SPLITK; s++) v += g_SK[(size_t)s*M*N + i];
    if (bias)  v += bias[n];
    if (resid) v += resid[i];
    C[i] = v;
}

// ---------------- driver ------------------------------------------------------
static float* sym(const void* s){ void* p = nullptr; cudaGetSymbolAddress(&p, s); return (float*)p; }

extern "C" void kernel_launch(void* const* d_in, const int* in_sizes, int n_in,
                              void* d_out, int out_size)
{
    const int*            ids   = (const int*)d_in[0];
    const unsigned char*  mask  = (const unsigned char*)d_in[1];
    const float*          emb   = (const float*)d_in[2];
    const float*          wi    = (const float*)d_in[3];   // [L, DIP, DMODEL]
    const float*          cw    = (const float*)d_in[4];   // [L, CONVDIM, 4]
    const float*          cb    = (const float*)d_in[5];
    const float*          dtb   = (const float*)d_in[6];
    const float*          alog  = (const float*)d_in[7];
    const float*          dss   = (const float*)d_in[8];
    const float*          nw    = (const float*)d_in[9];
    const float*          wo    = (const float*)d_in[10];  // [L, DMODEL, DINNER]
    const float*          aggw  = (const float*)d_in[11];  // [DMODEL, 2*DMODEL]
    const float*          aggb  = (const float*)d_in[12];
    const float*          nfw   = (const float*)d_in[13];
    const float*          lmw   = (const float*)d_in[14];  // [VOCAB, DMODEL]
    const float*          lmb   = (const float*)d_in[15];
    float*                out   = (float*)d_out;

    float* pXcat = sym(g_Xcat);
    float* pZ    = sym(g_Z);
    float* pyn   = sym(g_yn);
    float* pYcat = sym(g_Ycat);
    float* pXC   = sym(g_XC);
    float* pG    = sym(g_G);
    float* pH    = sym(g_H);

    k_lengths<<<BATCH, 256>>>(mask);
    k_embed<<<(MT*DMODEL + 255)/256, 256>>>(ids, emb);

    for (int l = 0; l < 2; l++){
        k_build_xcat<<<(M1*DMODEL + 255)/256, 256>>>();

        // zxbcdt = Xcat @ Wi^T   (M1 x DIP, K=DMODEL)
        k_gemm<<<dim3((DIP + BN - 1)/BN, M1/BM), 256>>>(
            pXcat, wi + (size_t)l*DIP*DMODEL, nullptr, nullptr, pZ, M1, DIP, DMODEL);

        k_conv<<<(M1*CONVDIM + 255)/256, 256>>>(cw + (size_t)l*CONVDIM*DCONV,
                                                cb + (size_t)l*CONVDIM);
        k_dt<<<(M1*NHEADS + 255)/256, 256>>>(dtb + l*NHEADS, alog + l*NHEADS);

        k_scan<<<VB*NHEADS, 256>>>(dss + l*NHEADS);

        k_gnorm<<<M1, 256>>>(nw + (size_t)l*DINNER);

        // Ycat = yn @ Wo^T + Xcat   (M1 x DMODEL, K=DINNER) — split-K
        k_gemm_sk<<<dim3(DMODEL/BN, M1/BM, SPLITK), 256>>>(
            pyn, wo + (size_t)l*DMODEL*DINNER, M1, DMODEL, DINNER);
        k_sk_reduce<<<(M1*DMODEL + 255)/256, 256>>>(nullptr, pXcat, pYcat, M1, DMODEL);

        k_unflip<<<(MT*DMODEL + 255)/256, 256>>>();

        // gate logits = [Xf|Xb] @ aggr_w^T + aggr_b   (MT x DMODEL, K=2*DMODEL) — split-K
        k_gemm_sk<<<dim3(DMODEL/BN, MT/BM, SPLITK), 256>>>(
            pXC, aggw, MT, DMODEL, 2*DMODEL);
        k_sk_reduce<<<(MT*DMODEL + 255)/256, 256>>>(aggb, nullptr, pG, MT, DMODEL);

        k_combine<<<(MT*DMODEL + 255)/256, 256>>>();
    }

    k_rmsnorm_final<<<MT, 256>>>(nfw);

    // logits = H @ lm_head_w^T + lm_head_b   (MT x VOCAB, K=DMODEL)
    k_gemm<<<dim3(VOCAB/BN, MT/BM), 256>>>(
        pH, lmw, lmb, nullptr, out, MT, VOCAB, DMODEL);

    (void)n_in; (void)in_sizes; (void)out_size;
}